// round 15
// baseline (speedup 1.0000x reference)
#include <cuda_runtime.h>
#include <cuda_fp16.h>
#include <cstdint>
#include <math.h>

// Problem constants (fixed by dataset)
#define T_TOTAL 8192
#define HID     2048
#define NEXP    8
#define INTER_N 4096
#define CAP     8192

// GEMM tiling
#define BM 256         // M-tile (both GEMMs)
#define BN 64          // gateup N-tile
#define BND 128        // down N-tile
#define BK 64
#define BKP (BK + 8)
#define NSTAGE 3
#define NTHR 512

// ---------------- scratch (device globals: allocation-free) ----------------
__device__ int    g_cnt[NEXP];
__device__ int    g_tok[NEXP * CAP];
__device__ float  g_wt[NEXP * CAP];
__device__ __half g_xh[(size_t)T_TOTAL * HID];                 // x in fp16
__device__ __half g_wgt[(size_t)NEXP * INTER_N * HID];         // gate^T fp16 [E][I][H]
__device__ __half g_wut[(size_t)NEXP * INTER_N * HID];         // up^T   fp16 [E][I][H]
__device__ __half g_wdt[(size_t)NEXP * HID * INTER_N];         // down^T fp16 [E][H][I]
__device__ __half g_mid[(size_t)NEXP * CAP * INTER_N];         // silu(g)*u fp16

// ---------------- helpers ----------------
static __device__ __forceinline__ uint32_t smem_u32(const void* p) {
    return (uint32_t)__cvta_generic_to_shared(p);
}
#define CP16(dst_u32, src_ptr, sz) \
    asm volatile("cp.async.cg.shared.global [%0], [%1], 16, %2;\n" \
                 :: "r"(dst_u32), "l"(src_ptr), "r"(sz))
#define CP_COMMIT() asm volatile("cp.async.commit_group;\n")
#define CP_WAIT(n)  asm volatile("cp.async.wait_group %0;\n" :: "n"(n))

static __device__ __forceinline__ void ldsm_x4(uint32_t r[4], uint32_t addr) {
    asm volatile("ldmatrix.sync.aligned.m8n8.x4.shared.b16 {%0,%1,%2,%3}, [%4];"
                 : "=r"(r[0]), "=r"(r[1]), "=r"(r[2]), "=r"(r[3]) : "r"(addr));
}
static __device__ __forceinline__ void mma16816(float c[4], const uint32_t a[4],
                                                uint32_t b0, uint32_t b1) {
    asm volatile(
        "mma.sync.aligned.m16n8k16.row.col.f32.f16.f16.f32 "
        "{%0,%1,%2,%3}, {%4,%5,%6,%7}, {%8,%9}, {%0,%1,%2,%3};\n"
        : "+f"(c[0]), "+f"(c[1]), "+f"(c[2]), "+f"(c[3])
        : "r"(a[0]), "r"(a[1]), "r"(a[2]), "r"(a[3]), "r"(b0), "r"(b1));
}

// ---------------- pre-pass: x -> fp16 ----------------
__global__ void cvt_x_kernel(const float* __restrict__ x) {
    size_t i = (size_t)blockIdx.x * blockDim.x + threadIdx.x;
    float4 v = reinterpret_cast<const float4*>(x)[i];
    __half2 h0 = __floats2half2_rn(v.x, v.y);
    __half2 h1 = __floats2half2_rn(v.z, v.w);
    uint2 u;
    u.x = *reinterpret_cast<uint32_t*>(&h0);
    u.y = *reinterpret_cast<uint32_t*>(&h1);
    reinterpret_cast<uint2*>(g_xh)[i] = u;
}

// ---------------- pre-pass: transpose + convert weight [R][C]f32 -> [C][R]f16 ----------------
__global__ void transpose_cvt_kernel(const float* __restrict__ in, __half* __restrict__ out,
                                     int R, int C) {
    __shared__ float tile[32][33];
    size_t base = (size_t)blockIdx.z * R * C;
    const float* inp = in + base;
    __half* outp = out + base;
    int c0 = blockIdx.x * 32, r0 = blockIdx.y * 32;
#pragma unroll
    for (int i = 0; i < 4; i++) {
        int r = r0 + threadIdx.y + i * 8;
        tile[threadIdx.y + i * 8][threadIdx.x] = inp[(size_t)r * C + c0 + threadIdx.x];
    }
    __syncthreads();
#pragma unroll
    for (int i = 0; i < 4; i++) {
        int c = c0 + threadIdx.y + i * 8;
        outp[(size_t)c * R + r0 + threadIdx.x] =
            __float2half(tile[threadIdx.x][threadIdx.y + i * 8]);
    }
}

// ---------------- phase 0/1: router ----------------
__global__ void zero_cnt_kernel() {
    if (threadIdx.x < NEXP) g_cnt[threadIdx.x] = 0;
}

__global__ void router_kernel(const float* __restrict__ x, const float* __restrict__ wr) {
    int lane = threadIdx.x & 31;
    int t = blockIdx.x * (blockDim.x >> 5) + (threadIdx.x >> 5);
    if (t >= T_TOTAL) return;
    const float* xr = x + (size_t)t * HID;
    float acc[NEXP];
#pragma unroll
    for (int e = 0; e < NEXP; e++) acc[e] = 0.f;
    for (int k = lane; k < HID; k += 32) {
        float xv = xr[k];
        const float* w = wr + (size_t)k * NEXP;
#pragma unroll
        for (int e = 0; e < NEXP; e++) acc[e] += xv * w[e];
    }
#pragma unroll
    for (int e = 0; e < NEXP; e++) {
#pragma unroll
        for (int s = 16; s > 0; s >>= 1) acc[e] += __shfl_xor_sync(0xffffffffu, acc[e], s);
    }
    if (lane == 0) {
        float mx = acc[0];
#pragma unroll
        for (int e = 1; e < NEXP; e++) mx = fmaxf(mx, acc[e]);
        float ex[NEXP]; float s = 0.f;
#pragma unroll
        for (int e = 0; e < NEXP; e++) { ex[e] = expf(acc[e] - mx); s += ex[e]; }
        float inv = 1.f / s;
        int i1 = 0; float p1 = ex[0] * inv;
#pragma unroll
        for (int e = 1; e < NEXP; e++) { float p = ex[e] * inv; if (p > p1) { p1 = p; i1 = e; } }
        int i2 = -1; float p2 = -1.f;
#pragma unroll
        for (int e = 0; e < NEXP; e++) {
            if (e == i1) continue;
            float p = ex[e] * inv; if (p > p2) { p2 = p; i2 = e; }
        }
        int pos1 = atomicAdd(&g_cnt[i1], 1);
        g_tok[i1 * CAP + pos1] = t; g_wt[i1 * CAP + pos1] = p1;
        int pos2 = atomicAdd(&g_cnt[i2], 1);
        g_tok[i2 * CAP + pos2] = t; g_wt[i2 * CAP + pos2] = p2;
    }
}

// ---------------- phase 2: gate+up GEMM (BM=256, 512 threads, 3-stage) ----------------
__global__ void __launch_bounds__(NTHR, 1) gateup_kernel() {
    int e = blockIdx.z;
    int cnt = g_cnt[e];
    int m0 = blockIdx.x * BM;
    if (m0 >= cnt) return;
    int n0 = blockIdx.y * BN;

    extern __shared__ __half sh[];
    __half* As = sh;                          // [NSTAGE][BM][BKP]
    __half* Bg = As + NSTAGE * BM * BKP;      // [NSTAGE][BN][BKP]
    __half* Bu = Bg + NSTAGE * BN * BKP;      // [NSTAGE][BN][BKP]
    __shared__ int toks[BM];

    int tid = threadIdx.x;
    if (tid < BM) {
        int slot = m0 + tid;
        toks[tid] = (slot < cnt) ? g_tok[e * CAP + slot] : -1;
    }
    __syncthreads();

    const __half* wgt_e = g_wgt + ((size_t)e * INTER_N + n0) * HID;
    const __half* wut_e = g_wut + ((size_t)e * INTER_N + n0) * HID;

    auto load_tiles = [&](int buf, int k0) {
#pragma unroll
        for (int i = 0; i < 4; i++) {           // A: 256 rows x 8 chunks = 2048
            int idx = tid + i * NTHR;
            int r = idx >> 3, c = idx & 7;
            int tok = toks[r];
            const __half* src = g_xh + (size_t)(tok < 0 ? 0 : tok) * HID + k0 + c * 8;
            CP16(smem_u32(As + ((size_t)buf * BM + r) * BKP + c * 8), src, tok >= 0 ? 16 : 0);
        }
        {                                        // Bg/Bu: 64 rows x 8 chunks = 512 each
            int r = tid >> 3, c = tid & 7;
            CP16(smem_u32(Bg + ((size_t)buf * BN + r) * BKP + c * 8),
                 wgt_e + (size_t)r * HID + k0 + c * 8, 16);
            CP16(smem_u32(Bu + ((size_t)buf * BN + r) * BKP + c * 8),
                 wut_e + (size_t)r * HID + k0 + c * 8, 16);
        }
    };

    int warp = tid >> 5, lane = tid & 31;
    int wm = warp & 7, wn = warp >> 3;     // 8x2 warps, warp tile 32x32
    int g = lane >> 2, tg = lane & 3;

    int a_row = (lane & 15);
    int a_col = (lane & 16) >> 1;
    int b_row = (lane & 7) + ((lane & 16) >> 1);
    int b_col = (lane & 8);

    float accG[2][4][4], accU[2][4][4];
#pragma unroll
    for (int mi = 0; mi < 2; mi++)
#pragma unroll
        for (int ni = 0; ni < 4; ni++)
#pragma unroll
            for (int q = 0; q < 4; q++) { accG[mi][ni][q] = 0.f; accU[mi][ni][q] = 0.f; }

    load_tiles(0, 0);        CP_COMMIT();
    load_tiles(1, BK);       CP_COMMIT();

    const int NT = HID / BK;   // 32
    for (int it = 0; it < NT; it++) {
        if (it + 1 < NT) CP_WAIT(1); else CP_WAIT(0);
        __syncthreads();

        int buf = it % NSTAGE;
        const __half* A  = As + (size_t)buf * BM * BKP;
        const __half* BG = Bg + (size_t)buf * BN * BKP;
        const __half* BU = Bu + (size_t)buf * BN * BKP;
#pragma unroll
        for (int kk = 0; kk < BK; kk += 16) {
            uint32_t a[2][4];
#pragma unroll
            for (int mi = 0; mi < 2; mi++) {
                ldsm_x4(a[mi], smem_u32(A + (wm * 32 + mi * 16 + a_row) * BKP + kk + a_col));
            }
#pragma unroll
            for (int ni2 = 0; ni2 < 2; ni2++) {
                uint32_t bg[4], bu[4];
                ldsm_x4(bg, smem_u32(BG + (size_t)(wn * 32 + ni2 * 16 + b_row) * BKP + kk + b_col));
                ldsm_x4(bu, smem_u32(BU + (size_t)(wn * 32 + ni2 * 16 + b_row) * BKP + kk + b_col));
#pragma unroll
                for (int mi = 0; mi < 2; mi++) {
                    mma16816(accG[mi][ni2 * 2 + 0], a[mi], bg[0], bg[1]);
                    mma16816(accG[mi][ni2 * 2 + 1], a[mi], bg[2], bg[3]);
                    mma16816(accU[mi][ni2 * 2 + 0], a[mi], bu[0], bu[1]);
                    mma16816(accU[mi][ni2 * 2 + 1], a[mi], bu[2], bu[3]);
                }
            }
        }
        if (it + 2 < NT) { load_tiles((it + 2) % NSTAGE, (it + 2) * BK); CP_COMMIT(); }
    }

    // epilogue: mid = silu(0.5*G) * U -> fp16 (half2 stores)
#pragma unroll
    for (int mi = 0; mi < 2; mi++) {
        int row0 = wm * 32 + mi * 16 + g;
#pragma unroll
        for (int part = 0; part < 2; part++) {
            int row = row0 + part * 8;
            int slot = m0 + row;
            if (slot < cnt) {
                __half* dst_row = g_mid + ((size_t)e * CAP + slot) * INTER_N + n0;
#pragma unroll
                for (int ni = 0; ni < 4; ni++) {
                    int col = wn * 32 + ni * 8 + tg * 2;
                    float g0 = accG[mi][ni][part * 2]     * 0.5f;
                    float g1 = accG[mi][ni][part * 2 + 1] * 0.5f;
                    float v0 = (g0 / (1.f + __expf(-g0))) * accU[mi][ni][part * 2];
                    float v1 = (g1 / (1.f + __expf(-g1))) * accU[mi][ni][part * 2 + 1];
                    *reinterpret_cast<__half2*>(dst_row + col) = __floats2half2_rn(v0, v1);
                }
            }
        }
    }
}

// ---------------- phase 3: down GEMM (BM=256, BND=128, 512 threads) ----------------
__global__ void __launch_bounds__(NTHR, 1) down_kernel(float* __restrict__ out) {
    int e = blockIdx.z;
    int cnt = g_cnt[e];
    int m0 = blockIdx.x * BM;
    if (m0 >= cnt) return;
    int n0 = blockIdx.y * BND;

    extern __shared__ __half sh[];
    __half* As = sh;                          // [NSTAGE][BM][BKP]
    __half* Bs = As + NSTAGE * BM * BKP;      // [NSTAGE][BND][BKP]
    __shared__ int toks[BM];
    __shared__ float wts[BM];

    int tid = threadIdx.x;
    if (tid < BM) {
        int slot = m0 + tid;
        toks[tid] = (slot < cnt) ? g_tok[e * CAP + slot] : -1;
        wts[tid]  = (slot < cnt) ? g_wt[e * CAP + slot] : 0.f;
    }
    __syncthreads();

    const __half* mid_e = g_mid + ((size_t)e * CAP) * INTER_N;
    const __half* wdt_e = g_wdt + ((size_t)e * HID + n0) * INTER_N;

    auto load_tiles = [&](int buf, int k0) {
#pragma unroll
        for (int i = 0; i < 4; i++) {           // A: 256 rows x 8 chunks
            int idx = tid + i * NTHR;
            int r = idx >> 3, c = idx & 7;
            bool valid = (m0 + r) < cnt;
            const __half* src = mid_e + (size_t)(valid ? m0 + r : 0) * INTER_N + k0 + c * 8;
            CP16(smem_u32(As + ((size_t)buf * BM + r) * BKP + c * 8), src, valid ? 16 : 0);
        }
#pragma unroll
        for (int i = 0; i < 2; i++) {           // B: 128 rows x 8 chunks
            int idx = tid + i * NTHR;
            int r = idx >> 3, c = idx & 7;
            CP16(smem_u32(Bs + ((size_t)buf * BND + r) * BKP + c * 8),
                 wdt_e + (size_t)r * INTER_N + k0 + c * 8, 16);
        }
    };

    int warp = tid >> 5, lane = tid & 31;
    int wm = warp & 7, wn = warp >> 3;     // 8x2 warps, warp tile 32x64
    int g = lane >> 2, tg = lane & 3;

    int a_row = (lane & 15);
    int a_col = (lane & 16) >> 1;
    int b_row = (lane & 7) + ((lane & 16) >> 1);
    int b_col = (lane & 8);

    float acc[2][8][4];
#pragma unroll
    for (int mi = 0; mi < 2; mi++)
#pragma unroll
        for (int ni = 0; ni < 8; ni++)
#pragma unroll
            for (int q = 0; q < 4; q++) acc[mi][ni][q] = 0.f;

    load_tiles(0, 0);        CP_COMMIT();
    load_tiles(1, BK);       CP_COMMIT();

    const int NT = INTER_N / BK;   // 64
    for (int it = 0; it < NT; it++) {
        if (it + 1 < NT) CP_WAIT(1); else CP_WAIT(0);
        __syncthreads();

        int buf = it % NSTAGE;
        const __half* A = As + (size_t)buf * BM * BKP;
        const __half* B = Bs + (size_t)buf * BND * BKP;
#pragma unroll
        for (int kk = 0; kk < BK; kk += 16) {
            uint32_t a[2][4];
#pragma unroll
            for (int mi = 0; mi < 2; mi++) {
                ldsm_x4(a[mi], smem_u32(A + (wm * 32 + mi * 16 + a_row) * BKP + kk + a_col));
            }
#pragma unroll
            for (int ni2 = 0; ni2 < 4; ni2++) {
                uint32_t b[4];
                ldsm_x4(b, smem_u32(B + (size_t)(wn * 64 + ni2 * 16 + b_row) * BKP + kk + b_col));
#pragma unroll
                for (int mi = 0; mi < 2; mi++) {
                    mma16816(acc[mi][ni2 * 2 + 0], a[mi], b[0], b[1]);
                    mma16816(acc[mi][ni2 * 2 + 1], a[mi], b[2], b[3]);
                }
            }
        }
        if (it + 2 < NT) { load_tiles((it + 2) % NSTAGE, (it + 2) * BK); CP_COMMIT(); }
    }

    // epilogue: out[token] += w_e * 0.25 * acc
#pragma unroll
    for (int mi = 0; mi < 2; mi++) {
        int row0 = wm * 32 + mi * 16 + g;
#pragma unroll
        for (int part = 0; part < 2; part++) {
            int row = row0 + part * 8;
            int slot = m0 + row;
            if (slot < cnt) {
                int tok = toks[row];
                float w = wts[row] * 0.25f;
                float* dst = out + (size_t)tok * HID + n0;
#pragma unroll
                for (int ni = 0; ni < 8; ni++) {
                    int col = wn * 64 + ni * 8 + tg * 2;
                    atomicAdd(dst + col,     acc[mi][ni][part * 2]     * w);
                    atomicAdd(dst + col + 1, acc[mi][ni][part * 2 + 1] * w);
                }
            }
        }
    }
}

// ---------------- launch ----------------
extern "C" void kernel_launch(void* const* d_in, const int* in_sizes, int n_in,
                              void* d_out, int out_size) {
    (void)in_sizes; (void)n_in;
    const float* x  = (const float*)d_in[0];
    const float* wr = (const float*)d_in[1];
    const float* wg = (const float*)d_in[2];
    const float* wu = (const float*)d_in[3];
    const float* wd = (const float*)d_in[4];
    float* out = (float*)d_out;

    static const int SMEM_GU = (NSTAGE * (BM + 2 * BN) * BKP) * (int)sizeof(__half);   // ~166 KB
    static const int SMEM_DN = (NSTAGE * (BM + BND) * BKP) * (int)sizeof(__half);      // ~166 KB
    cudaFuncSetAttribute(gateup_kernel, cudaFuncAttributeMaxDynamicSharedMemorySize, SMEM_GU);
    cudaFuncSetAttribute(down_kernel,   cudaFuncAttributeMaxDynamicSharedMemorySize, SMEM_DN);

    cudaMemsetAsync(out, 0, (size_t)out_size * sizeof(float), 0);
    zero_cnt_kernel<<<1, 32>>>();

    // pre-passes
    cvt_x_kernel<<<(T_TOTAL * HID / 4) / 256, 256>>>(x);
    {
        __half* wgt; cudaGetSymbolAddress((void**)&wgt, g_wgt);
        __half* wut; cudaGetSymbolAddress((void**)&wut, g_wut);
        __half* wdt; cudaGetSymbolAddress((void**)&wdt, g_wdt);
        dim3 blk(32, 8);
        dim3 gg(INTER_N / 32, HID / 32, NEXP);   // gate/up: [H][I] -> [I][H]
        transpose_cvt_kernel<<<gg, blk>>>(wg, wgt, HID, INTER_N);
        transpose_cvt_kernel<<<gg, blk>>>(wu, wut, HID, INTER_N);
        dim3 gd(HID / 32, INTER_N / 32, NEXP);   // down: [I][H] -> [H][I]
        transpose_cvt_kernel<<<gd, blk>>>(wd, wdt, INTER_N, HID);
    }

    router_kernel<<<T_TOTAL / 8, 256>>>(x, wr);

    dim3 g2(CAP / BM, INTER_N / BN, NEXP);   // (32, 64, 8)
    gateup_kernel<<<g2, NTHR, SMEM_GU>>>();

    dim3 g3(CAP / BM, HID / BND, NEXP);      // (32, 16, 8)
    down_kernel<<<g3, NTHR, SMEM_DN>>>(out);
}

// round 16
// speedup vs baseline: 1.0940x; 1.0940x over previous
#include <cuda_runtime.h>
#include <cuda_fp16.h>
#include <cstdint>
#include <math.h>

// Problem constants (fixed by dataset)
#define T_TOTAL 8192
#define HID     2048
#define NEXP    8
#define INTER_N 4096
#define CAP     8192

// GEMM tiling (R12 champion config: BM=128, 2 CTA/SM, 3-stage)
#define BM 128
#define BN 64          // gateup N-tile
#define BND 128        // down N-tile
#define BK 64
#define BKP (BK + 8)   // A-tile row pitch (halves)
#define BNP (BN + 8)   // gateup B-tile row pitch
#define BNDP (BND + 8) // down B-tile row pitch
#define NSTAGE 3

// ---------------- scratch (device globals: allocation-free) ----------------
__device__ int    g_cnt[NEXP];
__device__ int    g_tok[NEXP * CAP];
__device__ float  g_wt[NEXP * CAP];
__device__ __half g_xh[(size_t)T_TOTAL * HID];                 // x fp16 [T][H]
__device__ __half g_wg16[(size_t)NEXP * HID * INTER_N];        // gate fp16 [E][H][I] (original layout)
__device__ __half g_wu16[(size_t)NEXP * HID * INTER_N];        // up   fp16 [E][H][I]
__device__ __half g_wd16[(size_t)NEXP * INTER_N * HID];        // down fp16 [E][I][H]
__device__ __half g_mid[(size_t)NEXP * CAP * INTER_N];         // silu(g)*u fp16

// ---------------- helpers ----------------
static __device__ __forceinline__ uint32_t smem_u32(const void* p) {
    return (uint32_t)__cvta_generic_to_shared(p);
}
#define CP16(dst_u32, src_ptr, sz) \
    asm volatile("cp.async.cg.shared.global [%0], [%1], 16, %2;\n" \
                 :: "r"(dst_u32), "l"(src_ptr), "r"(sz))
#define CP_COMMIT() asm volatile("cp.async.commit_group;\n")
#define CP_WAIT(n)  asm volatile("cp.async.wait_group %0;\n" :: "n"(n))

static __device__ __forceinline__ void ldsm_x4(uint32_t r[4], uint32_t addr) {
    asm volatile("ldmatrix.sync.aligned.m8n8.x4.shared.b16 {%0,%1,%2,%3}, [%4];"
                 : "=r"(r[0]), "=r"(r[1]), "=r"(r[2]), "=r"(r[3]) : "r"(addr));
}
// trans variant: consumes row-major [k][n] tiles, yields mma B fragments directly
static __device__ __forceinline__ void ldsm_x4_t(uint32_t r[4], uint32_t addr) {
    asm volatile("ldmatrix.sync.aligned.m8n8.x4.trans.shared.b16 {%0,%1,%2,%3}, [%4];"
                 : "=r"(r[0]), "=r"(r[1]), "=r"(r[2]), "=r"(r[3]) : "r"(addr));
}
static __device__ __forceinline__ void mma16816(float c[4], const uint32_t a[4],
                                                uint32_t b0, uint32_t b1) {
    asm volatile(
        "mma.sync.aligned.m16n8k16.row.col.f32.f16.f16.f32 "
        "{%0,%1,%2,%3}, {%4,%5,%6,%7}, {%8,%9}, {%0,%1,%2,%3};\n"
        : "+f"(c[0]), "+f"(c[1]), "+f"(c[2]), "+f"(c[3])
        : "r"(a[0]), "r"(a[1]), "r"(a[2]), "r"(a[3]), "r"(b0), "r"(b1));
}

// ---------------- pre-pass: x -> fp16 ----------------
__global__ void cvt_x_kernel(const float* __restrict__ x) {
    size_t i = (size_t)blockIdx.x * blockDim.x + threadIdx.x;
    float4 v = reinterpret_cast<const float4*>(x)[i];
    __half2 h0 = __floats2half2_rn(v.x, v.y);
    __half2 h1 = __floats2half2_rn(v.z, v.w);
    uint2 u;
    u.x = *reinterpret_cast<uint32_t*>(&h0);
    u.y = *reinterpret_cast<uint32_t*>(&h1);
    reinterpret_cast<uint2*>(g_xh)[i] = u;
}

// ---------------- pre-pass: all three weights f32 -> f16, layout-preserving ----------------
__global__ void cvt_w_kernel(const float* __restrict__ wg, const float* __restrict__ wu,
                             const float* __restrict__ wd) {
    const size_t per = (size_t)NEXP * HID * INTER_N / 4;   // float4 groups per tensor
    size_t i = (size_t)blockIdx.x * blockDim.x + threadIdx.x;
    const float* src;
    __half* dst;
    size_t j;
    if (i < per)            { src = wg; dst = g_wg16; j = i; }
    else if (i < 2 * per)   { src = wu; dst = g_wu16; j = i - per; }
    else                    { src = wd; dst = g_wd16; j = i - 2 * per; }
    float4 v = reinterpret_cast<const float4*>(src)[j];
    __half2 h0 = __floats2half2_rn(v.x, v.y);
    __half2 h1 = __floats2half2_rn(v.z, v.w);
    uint2 u;
    u.x = *reinterpret_cast<uint32_t*>(&h0);
    u.y = *reinterpret_cast<uint32_t*>(&h1);
    reinterpret_cast<uint2*>(dst)[j] = u;
}

// ---------------- phase 0/1: router ----------------
__global__ void zero_cnt_kernel() {
    if (threadIdx.x < NEXP) g_cnt[threadIdx.x] = 0;
}

__global__ void router_kernel(const float* __restrict__ x, const float* __restrict__ wr) {
    int lane = threadIdx.x & 31;
    int t = blockIdx.x * (blockDim.x >> 5) + (threadIdx.x >> 5);
    if (t >= T_TOTAL) return;
    const float* xr = x + (size_t)t * HID;
    float acc[NEXP];
#pragma unroll
    for (int e = 0; e < NEXP; e++) acc[e] = 0.f;
    for (int k = lane; k < HID; k += 32) {
        float xv = xr[k];
        const float* w = wr + (size_t)k * NEXP;
#pragma unroll
        for (int e = 0; e < NEXP; e++) acc[e] += xv * w[e];
    }
#pragma unroll
    for (int e = 0; e < NEXP; e++) {
#pragma unroll
        for (int s = 16; s > 0; s >>= 1) acc[e] += __shfl_xor_sync(0xffffffffu, acc[e], s);
    }
    if (lane == 0) {
        float mx = acc[0];
#pragma unroll
        for (int e = 1; e < NEXP; e++) mx = fmaxf(mx, acc[e]);
        float ex[NEXP]; float s = 0.f;
#pragma unroll
        for (int e = 0; e < NEXP; e++) { ex[e] = expf(acc[e] - mx); s += ex[e]; }
        float inv = 1.f / s;
        int i1 = 0; float p1 = ex[0] * inv;
#pragma unroll
        for (int e = 1; e < NEXP; e++) { float p = ex[e] * inv; if (p > p1) { p1 = p; i1 = e; } }
        int i2 = -1; float p2 = -1.f;
#pragma unroll
        for (int e = 0; e < NEXP; e++) {
            if (e == i1) continue;
            float p = ex[e] * inv; if (p > p2) { p2 = p; i2 = e; }
        }
        int pos1 = atomicAdd(&g_cnt[i1], 1);
        g_tok[i1 * CAP + pos1] = t; g_wt[i1 * CAP + pos1] = p1;
        int pos2 = atomicAdd(&g_cnt[i2], 1);
        g_tok[i2 * CAP + pos2] = t; g_wt[i2 * CAP + pos2] = p2;
    }
}

// ---------------- phase 2: gate+up GEMM (B row-major [k][n] + trans ldmatrix) ----------------
__global__ void __launch_bounds__(256, 2) gateup_kernel() {
    int e = blockIdx.z;
    int cnt = g_cnt[e];
    int m0 = blockIdx.x * BM;
    if (m0 >= cnt) return;
    int n0 = blockIdx.y * BN;

    extern __shared__ __half sh[];
    __half* As = sh;                          // [NSTAGE][BM][BKP]
    __half* Bg = As + NSTAGE * BM * BKP;      // [NSTAGE][BK][BNP]
    __half* Bu = Bg + NSTAGE * BK * BNP;      // [NSTAGE][BK][BNP]
    __shared__ int toks[BM];

    int tid = threadIdx.x;
    if (tid < BM) {
        int slot = m0 + tid;
        toks[tid] = (slot < cnt) ? g_tok[e * CAP + slot] : -1;
    }
    __syncthreads();

    // original layouts: [H][I] -> element [k][n] at k*INTER_N + n
    const __half* wg_e = g_wg16 + (size_t)e * HID * INTER_N + n0;
    const __half* wu_e = g_wu16 + (size_t)e * HID * INTER_N + n0;

    auto load_tiles = [&](int buf, int k0) {
#pragma unroll
        for (int i = 0; i < 4; i++) {           // A: 128 rows x 8 chunks
            int idx = tid + i * 256;
            int r = idx >> 3, c = idx & 7;
            int tok = toks[r];
            const __half* src = g_xh + (size_t)(tok < 0 ? 0 : tok) * HID + k0 + c * 8;
            CP16(smem_u32(As + ((size_t)buf * BM + r) * BKP + c * 8), src, tok >= 0 ? 16 : 0);
        }
#pragma unroll
        for (int i = 0; i < 2; i++) {           // Bg/Bu: 64 k-rows x 8 chunks each
            int idx = tid + i * 256;
            int r = idx >> 3, c = idx & 7;      // r = k offset, c*8 = n offset
            CP16(smem_u32(Bg + ((size_t)buf * BK + r) * BNP + c * 8),
                 wg_e + (size_t)(k0 + r) * INTER_N + c * 8, 16);
            CP16(smem_u32(Bu + ((size_t)buf * BK + r) * BNP + c * 8),
                 wu_e + (size_t)(k0 + r) * INTER_N + c * 8, 16);
        }
    };

    int warp = tid >> 5, lane = tid & 31;
    int wm = warp & 3, wn = warp >> 2;     // 4x2 warps, 32x32 tiles
    int g = lane >> 2, tg = lane & 3;

    int a_row = (lane & 15);
    int a_col = (lane & 16) >> 1;
    int b_k   = (lane & 15);               // trans-ldmatrix: k row within 16-group
    int b_n   = (lane & 16) >> 1;          // 0 or 8 (n half)

    float accG[2][4][4], accU[2][4][4];
#pragma unroll
    for (int mi = 0; mi < 2; mi++)
#pragma unroll
        for (int ni = 0; ni < 4; ni++)
#pragma unroll
            for (int q = 0; q < 4; q++) { accG[mi][ni][q] = 0.f; accU[mi][ni][q] = 0.f; }

    load_tiles(0, 0);        CP_COMMIT();
    load_tiles(1, BK);       CP_COMMIT();

    const int NT = HID / BK;   // 32
    for (int it = 0; it < NT; it++) {
        if (it + 1 < NT) CP_WAIT(1); else CP_WAIT(0);
        __syncthreads();

        int buf = it % NSTAGE;
        const __half* A  = As + (size_t)buf * BM * BKP;
        const __half* BG = Bg + (size_t)buf * BK * BNP;
        const __half* BU = Bu + (size_t)buf * BK * BNP;
#pragma unroll
        for (int kk = 0; kk < BK; kk += 16) {
            uint32_t a[2][4];
#pragma unroll
            for (int mi = 0; mi < 2; mi++) {
                ldsm_x4(a[mi], smem_u32(A + (wm * 32 + mi * 16 + a_row) * BKP + kk + a_col));
            }
#pragma unroll
            for (int ni2 = 0; ni2 < 2; ni2++) {
                uint32_t bg[4], bu[4];
                ldsm_x4_t(bg, smem_u32(BG + (size_t)(kk + b_k) * BNP + wn * 32 + ni2 * 16 + b_n));
                ldsm_x4_t(bu, smem_u32(BU + (size_t)(kk + b_k) * BNP + wn * 32 + ni2 * 16 + b_n));
#pragma unroll
                for (int mi = 0; mi < 2; mi++) {
                    mma16816(accG[mi][ni2 * 2 + 0], a[mi], bg[0], bg[1]);
                    mma16816(accG[mi][ni2 * 2 + 1], a[mi], bg[2], bg[3]);
                    mma16816(accU[mi][ni2 * 2 + 0], a[mi], bu[0], bu[1]);
                    mma16816(accU[mi][ni2 * 2 + 1], a[mi], bu[2], bu[3]);
                }
            }
        }
        if (it + 2 < NT) { load_tiles((it + 2) % NSTAGE, (it + 2) * BK); CP_COMMIT(); }
    }

    // epilogue: mid = silu(0.5*G) * U -> fp16 (half2 stores)
#pragma unroll
    for (int mi = 0; mi < 2; mi++) {
        int row0 = wm * 32 + mi * 16 + g;
#pragma unroll
        for (int part = 0; part < 2; part++) {
            int row = row0 + part * 8;
            int slot = m0 + row;
            if (slot < cnt) {
                __half* dst_row = g_mid + ((size_t)e * CAP + slot) * INTER_N + n0;
#pragma unroll
                for (int ni = 0; ni < 4; ni++) {
                    int col = wn * 32 + ni * 8 + tg * 2;
                    float g0 = accG[mi][ni][part * 2]     * 0.5f;
                    float g1 = accG[mi][ni][part * 2 + 1] * 0.5f;
                    float v0 = (g0 / (1.f + __expf(-g0))) * accU[mi][ni][part * 2];
                    float v1 = (g1 / (1.f + __expf(-g1))) * accU[mi][ni][part * 2 + 1];
                    *reinterpret_cast<__half2*>(dst_row + col) = __floats2half2_rn(v0, v1);
                }
            }
        }
    }
}

// ---------------- phase 3: down GEMM (BND=128, trans ldmatrix B) ----------------
__global__ void __launch_bounds__(256, 2) down_kernel(float* __restrict__ out) {
    int e = blockIdx.z;
    int cnt = g_cnt[e];
    int m0 = blockIdx.x * BM;
    if (m0 >= cnt) return;
    int n0 = blockIdx.y * BND;

    extern __shared__ __half sh[];
    __half* As = sh;                          // [NSTAGE][BM][BKP]
    __half* Bs = As + NSTAGE * BM * BKP;      // [NSTAGE][BK][BNDP]
    __shared__ int toks[BM];
    __shared__ float wts[BM];

    int tid = threadIdx.x;
    if (tid < BM) {
        int slot = m0 + tid;
        toks[tid] = (slot < cnt) ? g_tok[e * CAP + slot] : -1;
        wts[tid]  = (slot < cnt) ? g_wt[e * CAP + slot] : 0.f;
    }
    __syncthreads();

    const __half* mid_e = g_mid + ((size_t)e * CAP) * INTER_N;
    // original layout [I][H]: element [k][n] at k*HID + n
    const __half* wd_e = g_wd16 + (size_t)e * INTER_N * HID + n0;

    auto load_tiles = [&](int buf, int k0) {
#pragma unroll
        for (int i = 0; i < 4; i++) {           // A: 128 rows x 8 chunks
            int idx = tid + i * 256;
            int r = idx >> 3, c = idx & 7;
            bool valid = (m0 + r) < cnt;
            const __half* src = mid_e + (size_t)(valid ? m0 + r : 0) * INTER_N + k0 + c * 8;
            CP16(smem_u32(As + ((size_t)buf * BM + r) * BKP + c * 8), src, valid ? 16 : 0);
        }
#pragma unroll
        for (int i = 0; i < 4; i++) {           // B: 64 k-rows x 16 chunks (128 n)
            int idx = tid + i * 256;
            int r = idx >> 4, c = idx & 15;
            CP16(smem_u32(Bs + ((size_t)buf * BK + r) * BNDP + c * 8),
                 wd_e + (size_t)(k0 + r) * HID + c * 8, 16);
        }
    };

    int warp = tid >> 5, lane = tid & 31;
    int wm = warp & 3, wn = warp >> 2;     // 4x2 warps, warp tile 32x64
    int g = lane >> 2, tg = lane & 3;

    int a_row = (lane & 15);
    int a_col = (lane & 16) >> 1;
    int b_k   = (lane & 15);
    int b_n   = (lane & 16) >> 1;

    float acc[2][8][4];
#pragma unroll
    for (int mi = 0; mi < 2; mi++)
#pragma unroll
        for (int ni = 0; ni < 8; ni++)
#pragma unroll
            for (int q = 0; q < 4; q++) acc[mi][ni][q] = 0.f;

    load_tiles(0, 0);        CP_COMMIT();
    load_tiles(1, BK);       CP_COMMIT();

    const int NT = INTER_N / BK;   // 64
    for (int it = 0; it < NT; it++) {
        if (it + 1 < NT) CP_WAIT(1); else CP_WAIT(0);
        __syncthreads();

        int buf = it % NSTAGE;
        const __half* A = As + (size_t)buf * BM * BKP;
        const __half* B = Bs + (size_t)buf * BK * BNDP;
#pragma unroll
        for (int kk = 0; kk < BK; kk += 16) {
            uint32_t a[2][4];
#pragma unroll
            for (int mi = 0; mi < 2; mi++) {
                ldsm_x4(a[mi], smem_u32(A + (wm * 32 + mi * 16 + a_row) * BKP + kk + a_col));
            }
#pragma unroll
            for (int ni2 = 0; ni2 < 4; ni2++) {
                uint32_t b[4];
                ldsm_x4_t(b, smem_u32(B + (size_t)(kk + b_k) * BNDP + wn * 64 + ni2 * 16 + b_n));
#pragma unroll
                for (int mi = 0; mi < 2; mi++) {
                    mma16816(acc[mi][ni2 * 2 + 0], a[mi], b[0], b[1]);
                    mma16816(acc[mi][ni2 * 2 + 1], a[mi], b[2], b[3]);
                }
            }
        }
        if (it + 2 < NT) { load_tiles((it + 2) % NSTAGE, (it + 2) * BK); CP_COMMIT(); }
    }

    // epilogue: out[token] += w_e * 0.25 * acc
#pragma unroll
    for (int mi = 0; mi < 2; mi++) {
        int row0 = wm * 32 + mi * 16 + g;
#pragma unroll
        for (int part = 0; part < 2; part++) {
            int row = row0 + part * 8;
            int slot = m0 + row;
            if (slot < cnt) {
                int tok = toks[row];
                float w = wts[row] * 0.25f;
                float* dst = out + (size_t)tok * HID + n0;
#pragma unroll
                for (int ni = 0; ni < 8; ni++) {
                    int col = wn * 64 + ni * 8 + tg * 2;
                    atomicAdd(dst + col,     acc[mi][ni][part * 2]     * w);
                    atomicAdd(dst + col + 1, acc[mi][ni][part * 2 + 1] * w);
                }
            }
        }
    }
}

// ---------------- launch ----------------
extern "C" void kernel_launch(void* const* d_in, const int* in_sizes, int n_in,
                              void* d_out, int out_size) {
    (void)in_sizes; (void)n_in;
    const float* x  = (const float*)d_in[0];
    const float* wr = (const float*)d_in[1];
    const float* wg = (const float*)d_in[2];
    const float* wu = (const float*)d_in[3];
    const float* wd = (const float*)d_in[4];
    float* out = (float*)d_out;

    static const int SMEM_GU = (NSTAGE * (BM * BKP + 2 * BK * BNP)) * (int)sizeof(__half);  // ~109 KB
    static const int SMEM_DN = (NSTAGE * (BM * BKP + BK * BNDP)) * (int)sizeof(__half);     // ~105 KB
    cudaFuncSetAttribute(gateup_kernel, cudaFuncAttributeMaxDynamicSharedMemorySize, SMEM_GU);
    cudaFuncSetAttribute(down_kernel,   cudaFuncAttributeMaxDynamicSharedMemorySize, SMEM_DN);

    cudaMemsetAsync(out, 0, (size_t)out_size * sizeof(float), 0);
    zero_cnt_kernel<<<1, 32>>>();

    // pre-passes (layout-preserving converts only; no transposes)
    cvt_x_kernel<<<(T_TOTAL * HID / 4) / 256, 256>>>(x);
    {
        const size_t per = (size_t)NEXP * HID * INTER_N / 4;
        cvt_w_kernel<<<(unsigned)(3 * per / 256), 256>>>(wg, wu, wd);
    }

    router_kernel<<<T_TOTAL / 8, 256>>>(x, wr);

    dim3 g2(CAP / BM, INTER_N / BN, NEXP);   // (64, 64, 8)
    gateup_kernel<<<g2, 256, SMEM_GU>>>();

    dim3 g3(CAP / BM, HID / BND, NEXP);      // (64, 16, 8)
    down_kernel<<<g3, 256, SMEM_DN>>>(out);
}

// round 17
// speedup vs baseline: 1.1388x; 1.0409x over previous
#include <cuda_runtime.h>
#include <cuda_fp16.h>
#include <cstdint>
#include <math.h>

// Problem constants (fixed by dataset)
#define T_TOTAL 8192
#define HID     2048
#define NEXP    8
#define INTER_N 4096
#define CAP     8192

// GEMM tiling (champion config: BM=128, 2 CTA/SM, 3-stage)
#define BM 128
#define BN 64          // gateup N-tile
#define BND 128        // down N-tile
#define BK 64
#define BKP (BK + 8)   // A-tile row pitch (halves)
#define BNP (BN + 8)   // gateup B-tile row pitch
#define BNDP (BND + 8) // down B-tile row pitch
#define NSTAGE 3

// ---------------- scratch (device globals: allocation-free) ----------------
__device__ int    g_cnt[NEXP];
__device__ int    g_tok[NEXP * CAP];
__device__ float  g_wt[NEXP * CAP];
__device__ __half g_xh[(size_t)T_TOTAL * HID];                 // x fp16 [T][H]
__device__ __half g_wg16[(size_t)NEXP * HID * INTER_N];        // gate fp16 [E][H][I]
__device__ __half g_wu16[(size_t)NEXP * HID * INTER_N];        // up   fp16 [E][H][I]
__device__ __half g_wd16[(size_t)NEXP * INTER_N * HID];        // down fp16 [E][I][H]
__device__ __half g_mid[(size_t)NEXP * CAP * INTER_N];         // silu(g)*u fp16

// ---------------- helpers ----------------
static __device__ __forceinline__ uint32_t smem_u32(const void* p) {
    return (uint32_t)__cvta_generic_to_shared(p);
}
#define CP16(dst_u32, src_ptr, sz) \
    asm volatile("cp.async.cg.shared.global [%0], [%1], 16, %2;\n" \
                 :: "r"(dst_u32), "l"(src_ptr), "r"(sz))
#define CP_COMMIT() asm volatile("cp.async.commit_group;\n")
#define CP_WAIT(n)  asm volatile("cp.async.wait_group %0;\n" :: "n"(n))

static __device__ __forceinline__ void ldsm_x4(uint32_t r[4], uint32_t addr) {
    asm volatile("ldmatrix.sync.aligned.m8n8.x4.shared.b16 {%0,%1,%2,%3}, [%4];"
                 : "=r"(r[0]), "=r"(r[1]), "=r"(r[2]), "=r"(r[3]) : "r"(addr));
}
static __device__ __forceinline__ void ldsm_x4_t(uint32_t r[4], uint32_t addr) {
    asm volatile("ldmatrix.sync.aligned.m8n8.x4.trans.shared.b16 {%0,%1,%2,%3}, [%4];"
                 : "=r"(r[0]), "=r"(r[1]), "=r"(r[2]), "=r"(r[3]) : "r"(addr));
}
static __device__ __forceinline__ void mma16816(float c[4], const uint32_t a[4],
                                                uint32_t b0, uint32_t b1) {
    asm volatile(
        "mma.sync.aligned.m16n8k16.row.col.f32.f16.f16.f32 "
        "{%0,%1,%2,%3}, {%4,%5,%6,%7}, {%8,%9}, {%0,%1,%2,%3};\n"
        : "+f"(c[0]), "+f"(c[1]), "+f"(c[2]), "+f"(c[3])
        : "r"(a[0]), "r"(a[1]), "r"(a[2]), "r"(a[3]), "r"(b0), "r"(b1));
}

// packed f32x2 (Blackwell FFMA2; plain sm_100+ feature, not arch-'a' gated)
static __device__ __forceinline__ uint64_t pack_f2(float a, float b) {
    uint64_t r;
    asm("mov.b64 %0, {%1, %2};" : "=l"(r) : "f"(a), "f"(b));
    return r;
}
#define FMA2(acc, xv, wv) \
    asm("fma.rn.f32x2 %0, %1, %2, %0;" : "+l"(acc) : "l"(xv), "l"(wv))

// ---------------- pre-pass: all three weights f32 -> f16, layout-preserving ----------------
__global__ void cvt_w_kernel(const float* __restrict__ wg, const float* __restrict__ wu,
                             const float* __restrict__ wd) {
    const size_t per = (size_t)NEXP * HID * INTER_N / 4;   // float4 groups per tensor
    size_t i = (size_t)blockIdx.x * blockDim.x + threadIdx.x;
    const float* src;
    __half* dst;
    size_t j;
    if (i < per)            { src = wg; dst = g_wg16; j = i; }
    else if (i < 2 * per)   { src = wu; dst = g_wu16; j = i - per; }
    else                    { src = wd; dst = g_wd16; j = i - 2 * per; }
    float4 v = reinterpret_cast<const float4*>(src)[j];
    __half2 h0 = __floats2half2_rn(v.x, v.y);
    __half2 h1 = __floats2half2_rn(v.z, v.w);
    uint2 u;
    u.x = *reinterpret_cast<uint32_t*>(&h0);
    u.y = *reinterpret_cast<uint32_t*>(&h1);
    reinterpret_cast<uint2*>(dst)[j] = u;
}

// ---------------- phase 0: zero bucket counts ----------------
__global__ void zero_cnt_kernel() {
    if (threadIdx.x < NEXP) g_cnt[threadIdx.x] = 0;
}

// ---------------- phase 1: router (wr in smem, f32x2 FMA, fused x->fp16) ----------------
// 64 tokens/CTA, 4 threads/token. Also converts x to g_xh (cvt_x fused).
#define RW_PITCH 9   // uint64 per packed-wr row: 72B -> q-lanes 4 banks apart
__global__ void __launch_bounds__(256, 1) router_kernel(const float* __restrict__ x,
                                                        const float* __restrict__ wr) {
    extern __shared__ uint64_t wr2[];   // [HID/2][RW_PITCH], only [..][0..7] used
    int tid = threadIdx.x;

    // cooperative load + pair-pack of w_router: wr2[p][e] = {wr[2p][e], wr[2p+1][e]}
    for (int p = tid; p < HID / 2; p += 256) {
        const float* r0 = wr + (size_t)(2 * p) * NEXP;
#pragma unroll
        for (int e = 0; e < NEXP; e++)
            wr2[p * RW_PITCH + e] = pack_f2(r0[e], r0[NEXP + e]);
    }
    __syncthreads();

    int t = blockIdx.x * 64 + (tid >> 2);
    int q = tid & 3;
    const float4* xr = reinterpret_cast<const float4*>(x + (size_t)t * HID);
    uint2* xo = reinterpret_cast<uint2*>(g_xh + (size_t)t * HID);

    uint64_t acc2[NEXP];
#pragma unroll
    for (int e = 0; e < NEXP; e++) acc2[e] = 0ull;

#pragma unroll 4
    for (int j = 0; j < 128; j++) {
        int k4 = j * 4 + q;              // float4 index; k = j*16 + q*4
        float4 v = xr[k4];
        // fused x -> fp16 store
        __half2 h0 = __floats2half2_rn(v.x, v.y);
        __half2 h1 = __floats2half2_rn(v.z, v.w);
        uint2 u;
        u.x = *reinterpret_cast<uint32_t*>(&h0);
        u.y = *reinterpret_cast<uint32_t*>(&h1);
        xo[k4] = u;
        // packed dot-product accumulation
        uint64_t xa = pack_f2(v.x, v.y), xb = pack_f2(v.z, v.w);
        int p = j * 8 + q * 2;
#pragma unroll
        for (int e = 0; e < NEXP; e++) {
            FMA2(acc2[e], xa, wr2[p * RW_PITCH + e]);
            FMA2(acc2[e], xb, wr2[(p + 1) * RW_PITCH + e]);
        }
    }

    float acc[NEXP];
#pragma unroll
    for (int e = 0; e < NEXP; e++) {
        float lo, hi;
        asm("mov.b64 {%0, %1}, %2;" : "=f"(lo), "=f"(hi) : "l"(acc2[e]));
        acc[e] = lo + hi;
    }
    // reduce across the 4 threads of this token (quad = lanes q^1, q^2)
#pragma unroll
    for (int e = 0; e < NEXP; e++) {
        acc[e] += __shfl_xor_sync(0xffffffffu, acc[e], 1);
        acc[e] += __shfl_xor_sync(0xffffffffu, acc[e], 2);
    }

    if (q == 0) {
        float mx = acc[0];
#pragma unroll
        for (int e = 1; e < NEXP; e++) mx = fmaxf(mx, acc[e]);
        float ex[NEXP]; float s = 0.f;
#pragma unroll
        for (int e = 0; e < NEXP; e++) { ex[e] = expf(acc[e] - mx); s += ex[e]; }
        float inv = 1.f / s;
        int i1 = 0; float p1 = ex[0] * inv;
#pragma unroll
        for (int e = 1; e < NEXP; e++) { float p = ex[e] * inv; if (p > p1) { p1 = p; i1 = e; } }
        int i2 = -1; float p2 = -1.f;
#pragma unroll
        for (int e = 0; e < NEXP; e++) {
            if (e == i1) continue;
            float p = ex[e] * inv; if (p > p2) { p2 = p; i2 = e; }
        }
        int pos1 = atomicAdd(&g_cnt[i1], 1);
        g_tok[i1 * CAP + pos1] = t; g_wt[i1 * CAP + pos1] = p1;
        int pos2 = atomicAdd(&g_cnt[i2], 1);
        g_tok[i2 * CAP + pos2] = t; g_wt[i2 * CAP + pos2] = p2;
    }
}

// ---------------- phase 2: gate+up GEMM (B row-major [k][n] + trans ldmatrix) ----------------
__global__ void __launch_bounds__(256, 2) gateup_kernel() {
    int e = blockIdx.z;
    int cnt = g_cnt[e];
    int m0 = blockIdx.x * BM;
    if (m0 >= cnt) return;
    int n0 = blockIdx.y * BN;

    extern __shared__ __half sh[];
    __half* As = sh;                          // [NSTAGE][BM][BKP]
    __half* Bg = As + NSTAGE * BM * BKP;      // [NSTAGE][BK][BNP]
    __half* Bu = Bg + NSTAGE * BK * BNP;      // [NSTAGE][BK][BNP]
    __shared__ int toks[BM];

    int tid = threadIdx.x;
    if (tid < BM) {
        int slot = m0 + tid;
        toks[tid] = (slot < cnt) ? g_tok[e * CAP + slot] : -1;
    }
    __syncthreads();

    const __half* wg_e = g_wg16 + (size_t)e * HID * INTER_N + n0;
    const __half* wu_e = g_wu16 + (size_t)e * HID * INTER_N + n0;

    auto load_tiles = [&](int buf, int k0) {
#pragma unroll
        for (int i = 0; i < 4; i++) {           // A: 128 rows x 8 chunks
            int idx = tid + i * 256;
            int r = idx >> 3, c = idx & 7;
            int tok = toks[r];
            const __half* src = g_xh + (size_t)(tok < 0 ? 0 : tok) * HID + k0 + c * 8;
            CP16(smem_u32(As + ((size_t)buf * BM + r) * BKP + c * 8), src, tok >= 0 ? 16 : 0);
        }
#pragma unroll
        for (int i = 0; i < 2; i++) {           // Bg/Bu: 64 k-rows x 8 chunks each
            int idx = tid + i * 256;
            int r = idx >> 3, c = idx & 7;
            CP16(smem_u32(Bg + ((size_t)buf * BK + r) * BNP + c * 8),
                 wg_e + (size_t)(k0 + r) * INTER_N + c * 8, 16);
            CP16(smem_u32(Bu + ((size_t)buf * BK + r) * BNP + c * 8),
                 wu_e + (size_t)(k0 + r) * INTER_N + c * 8, 16);
        }
    };

    int warp = tid >> 5, lane = tid & 31;
    int wm = warp & 3, wn = warp >> 2;     // 4x2 warps, 32x32 tiles
    int g = lane >> 2, tg = lane & 3;

    int a_row = (lane & 15);
    int a_col = (lane & 16) >> 1;
    int b_k   = (lane & 15);
    int b_n   = (lane & 16) >> 1;

    float accG[2][4][4], accU[2][4][4];
#pragma unroll
    for (int mi = 0; mi < 2; mi++)
#pragma unroll
        for (int ni = 0; ni < 4; ni++)
#pragma unroll
            for (int q = 0; q < 4; q++) { accG[mi][ni][q] = 0.f; accU[mi][ni][q] = 0.f; }

    load_tiles(0, 0);        CP_COMMIT();
    load_tiles(1, BK);       CP_COMMIT();

    const int NT = HID / BK;   // 32
    for (int it = 0; it < NT; it++) {
        if (it + 1 < NT) CP_WAIT(1); else CP_WAIT(0);
        __syncthreads();

        int buf = it % NSTAGE;
        const __half* A  = As + (size_t)buf * BM * BKP;
        const __half* BG = Bg + (size_t)buf * BK * BNP;
        const __half* BU = Bu + (size_t)buf * BK * BNP;
#pragma unroll
        for (int kk = 0; kk < BK; kk += 16) {
            uint32_t a[2][4];
#pragma unroll
            for (int mi = 0; mi < 2; mi++) {
                ldsm_x4(a[mi], smem_u32(A + (wm * 32 + mi * 16 + a_row) * BKP + kk + a_col));
            }
#pragma unroll
            for (int ni2 = 0; ni2 < 2; ni2++) {
                uint32_t bg[4], bu[4];
                ldsm_x4_t(bg, smem_u32(BG + (size_t)(kk + b_k) * BNP + wn * 32 + ni2 * 16 + b_n));
                ldsm_x4_t(bu, smem_u32(BU + (size_t)(kk + b_k) * BNP + wn * 32 + ni2 * 16 + b_n));
#pragma unroll
                for (int mi = 0; mi < 2; mi++) {
                    mma16816(accG[mi][ni2 * 2 + 0], a[mi], bg[0], bg[1]);
                    mma16816(accG[mi][ni2 * 2 + 1], a[mi], bg[2], bg[3]);
                    mma16816(accU[mi][ni2 * 2 + 0], a[mi], bu[0], bu[1]);
                    mma16816(accU[mi][ni2 * 2 + 1], a[mi], bu[2], bu[3]);
                }
            }
        }
        if (it + 2 < NT) { load_tiles((it + 2) % NSTAGE, (it + 2) * BK); CP_COMMIT(); }
    }

    // epilogue: mid = silu(0.5*G) * U -> fp16 (half2 stores)
#pragma unroll
    for (int mi = 0; mi < 2; mi++) {
        int row0 = wm * 32 + mi * 16 + g;
#pragma unroll
        for (int part = 0; part < 2; part++) {
            int row = row0 + part * 8;
            int slot = m0 + row;
            if (slot < cnt) {
                __half* dst_row = g_mid + ((size_t)e * CAP + slot) * INTER_N + n0;
#pragma unroll
                for (int ni = 0; ni < 4; ni++) {
                    int col = wn * 32 + ni * 8 + tg * 2;
                    float g0 = accG[mi][ni][part * 2]     * 0.5f;
                    float g1 = accG[mi][ni][part * 2 + 1] * 0.5f;
                    float v0 = (g0 / (1.f + __expf(-g0))) * accU[mi][ni][part * 2];
                    float v1 = (g1 / (1.f + __expf(-g1))) * accU[mi][ni][part * 2 + 1];
                    *reinterpret_cast<__half2*>(dst_row + col) = __floats2half2_rn(v0, v1);
                }
            }
        }
    }
}

// ---------------- phase 3: down GEMM (BND=128, trans ldmatrix B) ----------------
__global__ void __launch_bounds__(256, 2) down_kernel(float* __restrict__ out) {
    int e = blockIdx.z;
    int cnt = g_cnt[e];
    int m0 = blockIdx.x * BM;
    if (m0 >= cnt) return;
    int n0 = blockIdx.y * BND;

    extern __shared__ __half sh[];
    __half* As = sh;                          // [NSTAGE][BM][BKP]
    __half* Bs = As + NSTAGE * BM * BKP;      // [NSTAGE][BK][BNDP]
    __shared__ int toks[BM];
    __shared__ float wts[BM];

    int tid = threadIdx.x;
    if (tid < BM) {
        int slot = m0 + tid;
        toks[tid] = (slot < cnt) ? g_tok[e * CAP + slot] : -1;
        wts[tid]  = (slot < cnt) ? g_wt[e * CAP + slot] : 0.f;
    }
    __syncthreads();

    const __half* mid_e = g_mid + ((size_t)e * CAP) * INTER_N;
    const __half* wd_e = g_wd16 + (size_t)e * INTER_N * HID + n0;

    auto load_tiles = [&](int buf, int k0) {
#pragma unroll
        for (int i = 0; i < 4; i++) {           // A: 128 rows x 8 chunks
            int idx = tid + i * 256;
            int r = idx >> 3, c = idx & 7;
            bool valid = (m0 + r) < cnt;
            const __half* src = mid_e + (size_t)(valid ? m0 + r : 0) * INTER_N + k0 + c * 8;
            CP16(smem_u32(As + ((size_t)buf * BM + r) * BKP + c * 8), src, valid ? 16 : 0);
        }
#pragma unroll
        for (int i = 0; i < 4; i++) {           // B: 64 k-rows x 16 chunks (128 n)
            int idx = tid + i * 256;
            int r = idx >> 4, c = idx & 15;
            CP16(smem_u32(Bs + ((size_t)buf * BK + r) * BNDP + c * 8),
                 wd_e + (size_t)(k0 + r) * HID + c * 8, 16);
        }
    };

    int warp = tid >> 5, lane = tid & 31;
    int wm = warp & 3, wn = warp >> 2;     // 4x2 warps, warp tile 32x64
    int g = lane >> 2, tg = lane & 3;

    int a_row = (lane & 15);
    int a_col = (lane & 16) >> 1;
    int b_k   = (lane & 15);
    int b_n   = (lane & 16) >> 1;

    float acc[2][8][4];
#pragma unroll
    for (int mi = 0; mi < 2; mi++)
#pragma unroll
        for (int ni = 0; ni < 8; ni++)
#pragma unroll
            for (int q = 0; q < 4; q++) acc[mi][ni][q] = 0.f;

    load_tiles(0, 0);        CP_COMMIT();
    load_tiles(1, BK);       CP_COMMIT();

    const int NT = INTER_N / BK;   // 64
    for (int it = 0; it < NT; it++) {
        if (it + 1 < NT) CP_WAIT(1); else CP_WAIT(0);
        __syncthreads();

        int buf = it % NSTAGE;
        const __half* A = As + (size_t)buf * BM * BKP;
        const __half* B = Bs + (size_t)buf * BK * BNDP;
#pragma unroll
        for (int kk = 0; kk < BK; kk += 16) {
            uint32_t a[2][4];
#pragma unroll
            for (int mi = 0; mi < 2; mi++) {
                ldsm_x4(a[mi], smem_u32(A + (wm * 32 + mi * 16 + a_row) * BKP + kk + a_col));
            }
#pragma unroll
            for (int ni2 = 0; ni2 < 4; ni2++) {
                uint32_t b[4];
                ldsm_x4_t(b, smem_u32(B + (size_t)(kk + b_k) * BNDP + wn * 64 + ni2 * 16 + b_n));
#pragma unroll
                for (int mi = 0; mi < 2; mi++) {
                    mma16816(acc[mi][ni2 * 2 + 0], a[mi], b[0], b[1]);
                    mma16816(acc[mi][ni2 * 2 + 1], a[mi], b[2], b[3]);
                }
            }
        }
        if (it + 2 < NT) { load_tiles((it + 2) % NSTAGE, (it + 2) * BK); CP_COMMIT(); }
    }

    // epilogue: out[token] += w_e * 0.25 * acc
#pragma unroll
    for (int mi = 0; mi < 2; mi++) {
        int row0 = wm * 32 + mi * 16 + g;
#pragma unroll
        for (int part = 0; part < 2; part++) {
            int row = row0 + part * 8;
            int slot = m0 + row;
            if (slot < cnt) {
                int tok = toks[row];
                float w = wts[row] * 0.25f;
                float* dst = out + (size_t)tok * HID + n0;
#pragma unroll
                for (int ni = 0; ni < 8; ni++) {
                    int col = wn * 64 + ni * 8 + tg * 2;
                    atomicAdd(dst + col,     acc[mi][ni][part * 2]     * w);
                    atomicAdd(dst + col + 1, acc[mi][ni][part * 2 + 1] * w);
                }
            }
        }
    }
}

// ---------------- launch ----------------
extern "C" void kernel_launch(void* const* d_in, const int* in_sizes, int n_in,
                              void* d_out, int out_size) {
    (void)in_sizes; (void)n_in;
    const float* x  = (const float*)d_in[0];
    const float* wr = (const float*)d_in[1];
    const float* wg = (const float*)d_in[2];
    const float* wu = (const float*)d_in[3];
    const float* wd = (const float*)d_in[4];
    float* out = (float*)d_out;

    static const int SMEM_GU = (NSTAGE * (BM * BKP + 2 * BK * BNP)) * (int)sizeof(__half);
    static const int SMEM_DN = (NSTAGE * (BM * BKP + BK * BNDP)) * (int)sizeof(__half);
    static const int SMEM_RT = (HID / 2) * RW_PITCH * (int)sizeof(uint64_t);   // ~73.7 KB
    cudaFuncSetAttribute(gateup_kernel, cudaFuncAttributeMaxDynamicSharedMemorySize, SMEM_GU);
    cudaFuncSetAttribute(down_kernel,   cudaFuncAttributeMaxDynamicSharedMemorySize, SMEM_DN);
    cudaFuncSetAttribute(router_kernel, cudaFuncAttributeMaxDynamicSharedMemorySize, SMEM_RT);

    cudaMemsetAsync(out, 0, (size_t)out_size * sizeof(float), 0);
    zero_cnt_kernel<<<1, 32>>>();

    // weight convert (layout-preserving)
    {
        const size_t per = (size_t)NEXP * HID * INTER_N / 4;
        cvt_w_kernel<<<(unsigned)(3 * per / 256), 256>>>(wg, wu, wd);
    }

    // router + fused x->fp16 convert
    router_kernel<<<T_TOTAL / 64, 256, SMEM_RT>>>(x, wr);

    dim3 g2(CAP / BM, INTER_N / BN, NEXP);   // (64, 64, 8)
    gateup_kernel<<<g2, 256, SMEM_GU>>>();

    dim3 g3(CAP / BM, HID / BND, NEXP);      // (64, 16, 8)
    down_kernel<<<g3, 256, SMEM_DN>>>(out);
}